// round 12
// baseline (speedup 1.0000x reference)
#include <cuda_runtime.h>
#include <cuda_bf16.h>
#include <stdint.h>

// FlexAttention sliding-window + ALiBi via mma.sync bf16 hi/lo split.
// B=2, L=2048, H=16, E=64, W=1024. qkv [B,L,3,H,E] f32 -> out [B,L,H,E] f32.
//
// R8: 256 threads (8 warps x 16-row m-tiles), __launch_bounds__(256,2) ->
// 16 warps/SM. Softmax epilogue fused into the PV loop (P fragments built
// per 16-k chunk, never persisted) to fit the 128-reg budget.
// Everything else as R7: m16n8k16 bf16 MMA with hi/lo error-compensated
// split (3 MMAs per product), fixed-shift softmax p = 2^(s*log2e - 16),
// cp.async f32 staging -> per-tile bf16 conversion, XOR-swizzled smem.

#define LOG2E 1.44269504088896f

constexpr int Lc = 2048, Hc = 16, Ec = 64, Wc = 1024;
constexpr int BM = 128, BN = 64, THREADS = 256;
constexpr int TOK = 3072;  // floats per token

// word offsets (uint32 units). bf16 tiles: pitch 32 words (64 bf16), XOR swizzle.
constexpr int OQH = 0;       // Q hi [128 rows][32w]
constexpr int OQL = 4096;    // Q lo
constexpr int OKH = 8192;    // K hi [64][32w]   (rows = k, words = e-pairs)
constexpr int OKL = 10240;
constexpr int OVH = 12288;   // V^T hi [64 e][32w] (words = k-pairs)
constexpr int OVL = 14336;
constexpr int KSTG = 16384;  // K f32 staging [64][68]
constexpr int VSTG = KSTG + 64 * 68;
constexpr int SMEM_WORDS = VSTG + 64 * 68;
constexpr int SMEM_BYTES = SMEM_WORDS * 4;  // 100352

__device__ __forceinline__ uint32_t s2u(const void* p) {
    uint32_t a;
    asm("{.reg .u64 t; cvta.to.shared.u64 t,%1; cvt.u32.u64 %0,t;}" : "=r"(a) : "l"(p));
    return a;
}
__device__ __forceinline__ float ex2f(float x) {
    float y; asm("ex2.approx.ftz.f32 %0,%1;" : "=f"(y) : "f"(x)); return y;
}
// pack (a -> low half, b -> high half) as bf16x2, plus residual pack
__device__ __forceinline__ void splitpk(float a, float b, uint32_t& hi, uint32_t& lo) {
    uint32_t hw;
    asm("cvt.rn.bf16x2.f32 %0,%1,%2;" : "=r"(hw) : "f"(b), "f"(a));
    float ra = a - __uint_as_float(hw << 16);
    float rb = b - __uint_as_float(hw & 0xffff0000u);
    uint32_t lw;
    asm("cvt.rn.bf16x2.f32 %0,%1,%2;" : "=r"(lw) : "f"(rb), "f"(ra));
    hi = hw; lo = lw;
}
__device__ __forceinline__ void mma16816(float c[4], const uint32_t a[4],
                                         uint32_t b0, uint32_t b1) {
    asm volatile(
        "mma.sync.aligned.m16n8k16.row.col.f32.bf16.bf16.f32 "
        "{%0,%1,%2,%3},{%4,%5,%6,%7},{%8,%9},{%0,%1,%2,%3};"
        : "+f"(c[0]), "+f"(c[1]), "+f"(c[2]), "+f"(c[3])
        : "r"(a[0]), "r"(a[1]), "r"(a[2]), "r"(a[3]), "r"(b0), "r"(b1));
}
__device__ __forceinline__ void cp16(uint32_t dst, const void* src) {
    asm volatile("cp.async.cg.shared.global [%0], [%1], 16;" :: "r"(dst), "l"(src));
}
#define CP_COMMIT() asm volatile("cp.async.commit_group;" ::: "memory")
#define CP_WAIT0()  asm volatile("cp.async.wait_group 0;" ::: "memory")

__global__ __launch_bounds__(THREADS, 2) void flex_attn_mma(
    const float* __restrict__ qkv, float* __restrict__ out)
{
    extern __shared__ uint32_t smw[];
    const uint32_t sb = s2u(smw);
    const int tid = threadIdx.x, wid = tid >> 5, lane = tid & 31;
    const int g = lane >> 2, qd = lane & 3;          // mma groupID / tig
    const uint32_t xg = (uint32_t)g << 2;            // row swizzle (row&7 == g)
    const int m0 = 16 * wid;                         // warp's 16-row m-tile

    const int qtile = (int)gridDim.x - 1 - (int)blockIdx.x;  // heavy tiles first
    const int b = blockIdx.y >> 4, h = blockIdx.y & 15;
    const int q0 = qtile * BM;

    const float slope = ex2f(-0.5f * (float)(h + 1));
    const float sl2 = slope * LOG2E;
    const float qscale = 0.125f * LOG2E;

    const float* base = qkv + (int64_t)b * Lc * TOK + h * 64;
    const float* qb = base;
    const float* kb = base + 1024;
    const float* vb = base + 2048;

    const int kt0 = (q0 > Wc - 1) ? ((q0 - (Wc - 1)) >> 6) : 0;
    const int ktEnd = 2 * qtile + 1;

    // loader indexing: 4 threads per row, 16-float quarters
    const int lr = tid >> 2, lq = tid & 3;

    // ---- prologue: issue cp.async for first K/V tile ----
    {
        const int k0 = kt0 * BN;
        const float* ksrc = kb + (int64_t)(k0 + lr) * TOK + lq * 16;
        const float* vsrc = vb + (int64_t)(k0 + lr) * TOK + lq * 16;
        uint32_t kdst = sb + (uint32_t)(KSTG + lr * 68 + lq * 16) * 4u;
        uint32_t vdst = sb + (uint32_t)(VSTG + lr * 68 + lq * 16) * 4u;
#pragma unroll
        for (int i = 0; i < 4; i++) cp16(kdst + 16 * i, ksrc + 4 * i);
#pragma unroll
        for (int i = 0; i < 4; i++) cp16(vdst + 16 * i, vsrc + 4 * i);
        CP_COMMIT();
    }

    // ---- Q commit: 2 threads per row; scale, split, swizzled STS.128 ----
    {
        const int r = tid >> 1, hh = tid & 1;
        const uint32_t xr = (uint32_t)(r & 7) << 2;
        const float4* src = (const float4*)(qb + (int64_t)(q0 + r) * TOK) + 8 * hh;
        float f[32];
#pragma unroll
        for (int c = 0; c < 8; c++) {
            float4 v = src[c];
            f[4 * c + 0] = v.x * qscale; f[4 * c + 1] = v.y * qscale;
            f[4 * c + 2] = v.z * qscale; f[4 * c + 3] = v.w * qscale;
        }
#pragma unroll
        for (int m = 0; m < 4; m++) {
            uint32_t h4[4], l4[4];
#pragma unroll
            for (int j = 0; j < 4; j++)
                splitpk(f[8 * m + 2 * j], f[8 * m + 2 * j + 1], h4[j], l4[j]);
            uint32_t w = ((uint32_t)(16 * hh + 4 * m)) ^ xr;
            *(uint4*)(smw + OQH + r * 32 + w) = make_uint4(h4[0], h4[1], h4[2], h4[3]);
            *(uint4*)(smw + OQL + r * 32 + w) = make_uint4(l4[0], l4[1], l4[2], l4[3]);
        }
    }

    float O[8][4];
#pragma unroll
    for (int n = 0; n < 8; n++)
#pragma unroll
        for (int j = 0; j < 4; j++) O[n][j] = 0.f;
    float ls[2] = {0.f, 0.f};

    for (int kt = kt0; kt <= ktEnd; kt++) {
        const int k0 = kt * BN;

        CP_WAIT0();
        __syncthreads();  // staging arrived; prior-iter main-buf reads done

        // ---- convert K: (row, quarter) per thread; staging -> bf16 hi/lo ----
        {
            const uint32_t xr = (uint32_t)(lr & 7) << 2;
            const float4* srow = (const float4*)((const float*)(smw + KSTG) + lr * 68 + lq * 16);
            float f[16];
#pragma unroll
            for (int i = 0; i < 4; i++) {
                float4 v = srow[i];
                f[4 * i] = v.x; f[4 * i + 1] = v.y; f[4 * i + 2] = v.z; f[4 * i + 3] = v.w;
            }
#pragma unroll
            for (int m = 0; m < 2; m++) {
                uint32_t h4[4], l4[4];
#pragma unroll
                for (int j = 0; j < 4; j++)
                    splitpk(f[8 * m + 2 * j], f[8 * m + 2 * j + 1], h4[j], l4[j]);
                uint32_t w = ((uint32_t)(8 * lq + 4 * m)) ^ xr;
                *(uint4*)(smw + OKH + lr * 32 + w) = make_uint4(h4[0], h4[1], h4[2], h4[3]);
                *(uint4*)(smw + OKL + lr * 32 + w) = make_uint4(l4[0], l4[1], l4[2], l4[3]);
            }
        }
        // ---- convert V -> V^T: thread (kp, wv): pack k-pairs along words ----
        {
            const int kp = tid & 31, wv = tid >> 5;  // wv 0..7 -> 8 e each
            const float* r0 = (const float*)(smw + VSTG) + (2 * kp) * 68 + 8 * wv;
            const float* r1 = r0 + 68;
            float a0[8], a1[8];
#pragma unroll
            for (int i = 0; i < 2; i++) {
                float4 v0 = ((const float4*)r0)[i], v1 = ((const float4*)r1)[i];
                a0[4 * i] = v0.x; a0[4 * i + 1] = v0.y; a0[4 * i + 2] = v0.z; a0[4 * i + 3] = v0.w;
                a1[4 * i] = v1.x; a1[4 * i + 1] = v1.y; a1[4 * i + 2] = v1.z; a1[4 * i + 3] = v1.w;
            }
#pragma unroll
            for (int j = 0; j < 8; j++) {
                int e = 8 * wv + j;
                uint32_t hw, lw;
                splitpk(a0[j], a1[j], hw, lw);  // low = even k
                uint32_t w = (uint32_t)kp ^ ((uint32_t)(e & 7) << 2);
                smw[OVH + e * 32 + w] = hw;
                smw[OVL + e * 32 + w] = lw;
            }
        }
        __syncthreads();  // main bufs ready; staging free

        // ---- issue cp.async for next tile ----
        if (kt < ktEnd) {
            const int kn = k0 + BN;
            const float* ksrc = kb + (int64_t)(kn + lr) * TOK + lq * 16;
            const float* vsrc = vb + (int64_t)(kn + lr) * TOK + lq * 16;
            uint32_t kdst = sb + (uint32_t)(KSTG + lr * 68 + lq * 16) * 4u;
            uint32_t vdst = sb + (uint32_t)(VSTG + lr * 68 + lq * 16) * 4u;
#pragma unroll
            for (int i = 0; i < 4; i++) cp16(kdst + 16 * i, ksrc + 4 * i);
#pragma unroll
            for (int i = 0; i < 4; i++) cp16(vdst + 16 * i, vsrc + 4 * i);
            CP_COMMIT();
        }

        // ---- S = Q K^T : 4 k-steps x 8 n-tiles x 3 split-MMAs ----
        float S[8][4];
#pragma unroll
        for (int n = 0; n < 8; n++)
#pragma unroll
            for (int j = 0; j < 4; j++) S[n][j] = 0.f;

#pragma unroll
        for (int ks = 0; ks < 4; ks++) {
            const uint32_t wa = ((uint32_t)(ks * 8 + qd)) ^ xg;
            const uint32_t wb = wa ^ 4u;
            uint32_t AH[4], AL[4];
            {
                uint32_t rb0 = (uint32_t)(OQH + (m0 + g) * 32);
                AH[0] = smw[rb0 + wa];       AH[1] = smw[rb0 + 256 + wa];
                AH[2] = smw[rb0 + wb];       AH[3] = smw[rb0 + 256 + wb];
                uint32_t rb1 = rb0 + (OQL - OQH);
                AL[0] = smw[rb1 + wa];       AL[1] = smw[rb1 + 256 + wa];
                AL[2] = smw[rb1 + wb];       AL[3] = smw[rb1 + 256 + wb];
            }
#pragma unroll
            for (int n = 0; n < 8; n++) {
                uint32_t kbw = (uint32_t)(OKH + (8 * n + g) * 32);
                uint32_t bh0 = smw[kbw + wa], bh1 = smw[kbw + wb];
                uint32_t bl0 = smw[kbw + 2048 + wa], bl1 = smw[kbw + 2048 + wb];
                mma16816(S[n], AH, bh0, bh1);
                mma16816(S[n], AH, bl0, bl1);
                mma16816(S[n], AL, bh0, bh1);
            }
        }

        // ---- fused epilogue + PV: per 16-k chunk build P frags, then MMA ----
        const int qi0 = q0 + m0 + g;
#pragma unroll
        for (int kv = 0; kv < 4; kv++) {
            uint32_t PH[4], PL[4];
#pragma unroll
            for (int half = 0; half < 2; half++) {
                const int n = 2 * kv + half;
                const int d0 = qi0 - (k0 + 8 * n + 2 * qd);
                const float df0 = (float)d0;
                float e0 = fmaf(-sl2, df0,        S[n][0] - 16.0f);
                float e1 = fmaf(-sl2, df0 - 1.0f, S[n][1] - 16.0f);
                float e2 = fmaf(-sl2, df0 + 8.0f, S[n][2] - 16.0f);
                float e3 = fmaf(-sl2, df0 + 7.0f, S[n][3] - 16.0f);
                float p0 = ((unsigned)d0 < 1024u)       ? ex2f(e0) : 0.f;
                float p1 = ((unsigned)(d0 - 1) < 1024u) ? ex2f(e1) : 0.f;
                float p2 = ((unsigned)(d0 + 8) < 1024u) ? ex2f(e2) : 0.f;
                float p3 = ((unsigned)(d0 + 7) < 1024u) ? ex2f(e3) : 0.f;
                ls[0] += p0 + p1;
                ls[1] += p2 + p3;
                splitpk(p0, p1, PH[2 * half],     PL[2 * half]);
                splitpk(p2, p3, PH[2 * half + 1], PL[2 * half + 1]);
            }
            const uint32_t wa = ((uint32_t)(kv * 8 + qd)) ^ xg;
            const uint32_t wb = wa ^ 4u;
#pragma unroll
            for (int ne = 0; ne < 8; ne++) {
                uint32_t vbw = (uint32_t)(OVH + (8 * ne + g) * 32);
                uint32_t bh0 = smw[vbw + wa], bh1 = smw[vbw + wb];
                uint32_t bl0 = smw[vbw + 2048 + wa], bl1 = smw[vbw + 2048 + wb];
                mma16816(O[ne], PH, bh0, bh1);
                mma16816(O[ne], PH, bl0, bl1);
                mma16816(O[ne], PL, bh0, bh1);
            }
        }
    }

    // ---- normalize + store ----
#pragma unroll
    for (int rr = 0; rr < 2; rr++) {
        float s = ls[rr];
        s += __shfl_xor_sync(0xffffffffu, s, 1);
        s += __shfl_xor_sync(0xffffffffu, s, 2);
        const float inv = 1.0f / s;
        const int qrow = q0 + m0 + g + 8 * rr;
        float* op = out + (((int64_t)b * Lc + qrow) * Hc + h) * Ec + 2 * qd;
#pragma unroll
        for (int ne = 0; ne < 8; ne++) {
            float2 v;
            v.x = O[ne][2 * rr] * inv;
            v.y = O[ne][2 * rr + 1] * inv;
            *(float2*)(op + 8 * ne) = v;
        }
    }
}

extern "C" void kernel_launch(void* const* d_in, const int* in_sizes, int n_in,
                              void* d_out, int out_size)
{
    const float* qkv = (const float*)d_in[0];
    float* out = (float*)d_out;

    cudaFuncSetAttribute(flex_attn_mma,
                         cudaFuncAttributeMaxDynamicSharedMemorySize, SMEM_BYTES);

    dim3 grid(Lc / BM, 2 * Hc);  // 16 q-tiles x 32 (b,h)
    flex_attn_mma<<<grid, THREADS, SMEM_BYTES>>>(qkv, out);
}

// round 13
// speedup vs baseline: 1.4334x; 1.4334x over previous
#include <cuda_runtime.h>
#include <cuda_bf16.h>
#include <stdint.h>

// FlexAttention sliding-window + ALiBi via mma.sync bf16 hi/lo split.
// B=2, L=2048, H=16, E=64, W=1024. qkv [B,L,3,H,E] f32 -> out [B,L,H,E] f32.
//
// R13: R7 shape (4 warps x 32-row m-tiles, B-frag reuse x2) + 3 CTAs/SM.
//  - smem 64 KB (bf16 tiles only): K/V loaded LDG.128 -> split -> STS
//    (no f32 staging); inter-CTA staggering hides the load phase.
//  - per-kv-chunk restructure: S chunk accum (16 regs), epilogue + PV fused
//    per chunk; O persistent. ~150 regs -> __launch_bounds__(128,3).
//  - m16n8k16 bf16 MMA, hi/lo error-compensated split (3 MMAs/product),
//    fixed-shift softmax p = 2^(s*log2e - 16), XOR-swizzled smem.

#define LOG2E 1.44269504088896f

constexpr int Lc = 2048, Hc = 16, Ec = 64, Wc = 1024;
constexpr int BM = 128, BN = 64, THREADS = 128;
constexpr int TOK = 3072;  // floats per token

// word offsets (uint32 units). bf16 tiles: pitch 32 words (64 bf16), XOR swizzle.
constexpr int OQH = 0;       // Q hi [128 rows][32w]
constexpr int OQL = 4096;    // Q lo
constexpr int OKH = 8192;    // K hi [64][32w]   (rows = k, words = e-pairs)
constexpr int OKL = 10240;
constexpr int OVH = 12288;   // V^T hi [64 e][32w] (words = k-pairs)
constexpr int OVL = 14336;
constexpr int SMEM_WORDS = 16384;
constexpr int SMEM_BYTES = SMEM_WORDS * 4;  // 65536 -> 3 CTAs/SM

__device__ __forceinline__ float ex2f(float x) {
    float y; asm("ex2.approx.ftz.f32 %0,%1;" : "=f"(y) : "f"(x)); return y;
}
// pack (a -> low half, b -> high half) as bf16x2, plus residual pack
__device__ __forceinline__ void splitpk(float a, float b, uint32_t& hi, uint32_t& lo) {
    uint32_t hw;
    asm("cvt.rn.bf16x2.f32 %0,%1,%2;" : "=r"(hw) : "f"(b), "f"(a));
    float ra = a - __uint_as_float(hw << 16);
    float rb = b - __uint_as_float(hw & 0xffff0000u);
    uint32_t lw;
    asm("cvt.rn.bf16x2.f32 %0,%1,%2;" : "=r"(lw) : "f"(rb), "f"(ra));
    hi = hw; lo = lw;
}
__device__ __forceinline__ void mma16816(float c[4], const uint32_t a[4],
                                         uint32_t b0, uint32_t b1) {
    asm volatile(
        "mma.sync.aligned.m16n8k16.row.col.f32.bf16.bf16.f32 "
        "{%0,%1,%2,%3},{%4,%5,%6,%7},{%8,%9},{%0,%1,%2,%3};"
        : "+f"(c[0]), "+f"(c[1]), "+f"(c[2]), "+f"(c[3])
        : "r"(a[0]), "r"(a[1]), "r"(a[2]), "r"(a[3]), "r"(b0), "r"(b1));
}

__global__ __launch_bounds__(THREADS, 3) void flex_attn_mma(
    const float* __restrict__ qkv, float* __restrict__ out)
{
    extern __shared__ uint32_t smw[];
    const int tid = threadIdx.x, wid = tid >> 5, lane = tid & 31;
    const int g = lane >> 2, qd = lane & 3;          // mma groupID / tig
    const uint32_t xg = (uint32_t)g << 2;            // row swizzle (row&7 == g)
    const int m0 = 32 * wid;                         // warp's 32-row m-tile pair

    const int qtile = (int)gridDim.x - 1 - (int)blockIdx.x;  // heavy tiles first
    const int b = blockIdx.y >> 4, h = blockIdx.y & 15;
    const int q0 = qtile * BM;

    const float slope = ex2f(-0.5f * (float)(h + 1));
    const float sl2 = slope * LOG2E;
    const float qscale = 0.125f * LOG2E;

    const float* base = qkv + (int64_t)b * Lc * TOK + h * 64;
    const float* qb = base;
    const float* kb = base + 1024;
    const float* vb = base + 2048;

    const int kt0 = (q0 > Wc - 1) ? ((q0 - (Wc - 1)) >> 6) : 0;
    const int ktEnd = 2 * qtile + 1;

    // loader roles (each thread does one K half-row AND one V e-slab)
    const int kr = tid >> 1, khh = tid & 1;           // K: row, 32-float half
    const int vkp = tid & 31, vwv = tid >> 5;         // V: k-pair, 16-e slab

    // ---- Q commit: thread = row; scale, split, swizzled STS.128 ----
    {
        const int r = tid;
        const uint32_t xr = (uint32_t)(r & 7) << 2;
        const float4* src = (const float4*)(qb + (int64_t)(q0 + r) * TOK);
        float f[64];
#pragma unroll
        for (int c = 0; c < 16; c++) {
            float4 v = src[c];
            f[4 * c + 0] = v.x * qscale; f[4 * c + 1] = v.y * qscale;
            f[4 * c + 2] = v.z * qscale; f[4 * c + 3] = v.w * qscale;
        }
#pragma unroll
        for (int m = 0; m < 8; m++) {
            uint32_t h4[4], l4[4];
#pragma unroll
            for (int j = 0; j < 4; j++)
                splitpk(f[8 * m + 2 * j], f[8 * m + 2 * j + 1], h4[j], l4[j]);
            uint32_t w = ((uint32_t)(4 * m)) ^ xr;
            *(uint4*)(smw + OQH + r * 32 + w) = make_uint4(h4[0], h4[1], h4[2], h4[3]);
            *(uint4*)(smw + OQL + r * 32 + w) = make_uint4(l4[0], l4[1], l4[2], l4[3]);
        }
    }

    float O[2][8][4];
#pragma unroll
    for (int mt = 0; mt < 2; mt++)
#pragma unroll
        for (int n = 0; n < 8; n++)
#pragma unroll
            for (int j = 0; j < 4; j++) O[mt][n][j] = 0.f;
    float ls[2][2] = {{0.f, 0.f}, {0.f, 0.f}};

    for (int kt = kt0; kt <= ktEnd; kt++) {
        const int k0 = kt * BN;
        __syncthreads();  // prior-iter K/V reads complete before overwrite

        // ---- K load+convert: LDG.128 x8 -> split -> swizzled STS.128 ----
        {
            const float* ksrc = kb + (int64_t)(k0 + kr) * TOK + khh * 32;
            float f[32];
#pragma unroll
            for (int i = 0; i < 8; i++) {
                float4 v = ((const float4*)ksrc)[i];
                f[4 * i] = v.x; f[4 * i + 1] = v.y; f[4 * i + 2] = v.z; f[4 * i + 3] = v.w;
            }
            const uint32_t xr = (uint32_t)(kr & 7) << 2;
#pragma unroll
            for (int m = 0; m < 4; m++) {
                uint32_t h4[4], l4[4];
#pragma unroll
                for (int j = 0; j < 4; j++)
                    splitpk(f[8 * m + 2 * j], f[8 * m + 2 * j + 1], h4[j], l4[j]);
                uint32_t w = ((uint32_t)(16 * khh + 4 * m)) ^ xr;
                *(uint4*)(smw + OKH + kr * 32 + w) = make_uint4(h4[0], h4[1], h4[2], h4[3]);
                *(uint4*)(smw + OKL + kr * 32 + w) = make_uint4(l4[0], l4[1], l4[2], l4[3]);
            }
        }
        // ---- V load+convert -> V^T: rows 2kp,2kp+1, e slab [16wv,16wv+16) ----
        {
            const float* r0 = vb + (int64_t)(k0 + 2 * vkp) * TOK + 16 * vwv;
            const float* r1 = r0 + TOK;
            float a0[16], a1[16];
#pragma unroll
            for (int i = 0; i < 4; i++) {
                float4 v0 = ((const float4*)r0)[i], v1 = ((const float4*)r1)[i];
                a0[4 * i] = v0.x; a0[4 * i + 1] = v0.y; a0[4 * i + 2] = v0.z; a0[4 * i + 3] = v0.w;
                a1[4 * i] = v1.x; a1[4 * i + 1] = v1.y; a1[4 * i + 2] = v1.z; a1[4 * i + 3] = v1.w;
            }
#pragma unroll
            for (int j = 0; j < 16; j++) {
                int e = 16 * vwv + j;
                uint32_t hw, lw;
                splitpk(a0[j], a1[j], hw, lw);  // low = even k
                uint32_t w = (uint32_t)vkp ^ ((uint32_t)(e & 7) << 2);
                smw[OVH + e * 32 + w] = hw;
                smw[OVL + e * 32 + w] = lw;
            }
        }
        __syncthreads();  // tiles ready

        const int qi0 = q0 + m0 + g;

        // ---- per 16-k chunk: S-MMAs (full E), fused epilogue, PV-MMAs ----
#pragma unroll
        for (int kv = 0; kv < 4; kv++) {
            float S[2][2][4];
#pragma unroll
            for (int mt = 0; mt < 2; mt++)
#pragma unroll
                for (int nh = 0; nh < 2; nh++)
#pragma unroll
                    for (int j = 0; j < 4; j++) S[mt][nh][j] = 0.f;

#pragma unroll
            for (int ks = 0; ks < 4; ks++) {
                const uint32_t wa = ((uint32_t)(ks * 8 + qd)) ^ xg;
                const uint32_t wb = wa ^ 4u;
                uint32_t AH[2][4], AL[2][4];
#pragma unroll
                for (int mt = 0; mt < 2; mt++) {
                    uint32_t rb0 = (uint32_t)(OQH + (m0 + 16 * mt + g) * 32);
                    AH[mt][0] = smw[rb0 + wa];       AH[mt][1] = smw[rb0 + 256 + wa];
                    AH[mt][2] = smw[rb0 + wb];       AH[mt][3] = smw[rb0 + 256 + wb];
                    uint32_t rb1 = rb0 + (OQL - OQH);
                    AL[mt][0] = smw[rb1 + wa];       AL[mt][1] = smw[rb1 + 256 + wa];
                    AL[mt][2] = smw[rb1 + wb];       AL[mt][3] = smw[rb1 + 256 + wb];
                }
#pragma unroll
                for (int nh = 0; nh < 2; nh++) {
                    const int n = 2 * kv + nh;
                    uint32_t kbw = (uint32_t)(OKH + (8 * n + g) * 32);
                    uint32_t bh0 = smw[kbw + wa], bh1 = smw[kbw + wb];
                    uint32_t bl0 = smw[kbw + 2048 + wa], bl1 = smw[kbw + 2048 + wb];
#pragma unroll
                    for (int mt = 0; mt < 2; mt++) {
                        mma16816(S[mt][nh], AH[mt], bh0, bh1);
                        mma16816(S[mt][nh], AH[mt], bl0, bl1);
                        mma16816(S[mt][nh], AL[mt], bh0, bh1);
                    }
                }
            }

            // epilogue -> P fragments (A-frag layout of the 16-k chunk)
            uint32_t PH[2][4], PL[2][4];
#pragma unroll
            for (int mt = 0; mt < 2; mt++) {
                const int qi = qi0 + 16 * mt;
#pragma unroll
                for (int nh = 0; nh < 2; nh++) {
                    const int n = 2 * kv + nh;
                    const int d0 = qi - (k0 + 8 * n + 2 * qd);
                    const float df0 = (float)d0;
                    float e0 = fmaf(-sl2, df0,        S[mt][nh][0] - 16.0f);
                    float e1 = fmaf(-sl2, df0 - 1.0f, S[mt][nh][1] - 16.0f);
                    float e2 = fmaf(-sl2, df0 + 8.0f, S[mt][nh][2] - 16.0f);
                    float e3 = fmaf(-sl2, df0 + 7.0f, S[mt][nh][3] - 16.0f);
                    float p0 = ((unsigned)d0 < 1024u)       ? ex2f(e0) : 0.f;
                    float p1 = ((unsigned)(d0 - 1) < 1024u) ? ex2f(e1) : 0.f;
                    float p2 = ((unsigned)(d0 + 8) < 1024u) ? ex2f(e2) : 0.f;
                    float p3 = ((unsigned)(d0 + 7) < 1024u) ? ex2f(e3) : 0.f;
                    ls[mt][0] += p0 + p1;
                    ls[mt][1] += p2 + p3;
                    splitpk(p0, p1, PH[mt][2 * nh],     PL[mt][2 * nh]);
                    splitpk(p2, p3, PH[mt][2 * nh + 1], PL[mt][2 * nh + 1]);
                }
            }

            // PV for this 16-k chunk
            const uint32_t wa = ((uint32_t)(kv * 8 + qd)) ^ xg;
            const uint32_t wb = wa ^ 4u;
#pragma unroll
            for (int ne = 0; ne < 8; ne++) {
                uint32_t vbw = (uint32_t)(OVH + (8 * ne + g) * 32);
                uint32_t bh0 = smw[vbw + wa], bh1 = smw[vbw + wb];
                uint32_t bl0 = smw[vbw + 2048 + wa], bl1 = smw[vbw + 2048 + wb];
#pragma unroll
                for (int mt = 0; mt < 2; mt++) {
                    mma16816(O[mt][ne], PH[mt], bh0, bh1);
                    mma16816(O[mt][ne], PH[mt], bl0, bl1);
                    mma16816(O[mt][ne], PL[mt], bh0, bh1);
                }
            }
        }
    }

    // ---- normalize + store ----
#pragma unroll
    for (int mt = 0; mt < 2; mt++) {
#pragma unroll
        for (int rr = 0; rr < 2; rr++) {
            float s = ls[mt][rr];
            s += __shfl_xor_sync(0xffffffffu, s, 1);
            s += __shfl_xor_sync(0xffffffffu, s, 2);
            const float inv = 1.0f / s;
            const int qrow = q0 + m0 + 16 * mt + g + 8 * rr;
            float* op = out + (((int64_t)b * Lc + qrow) * Hc + h) * Ec + 2 * qd;
#pragma unroll
            for (int ne = 0; ne < 8; ne++) {
                float2 v;
                v.x = O[mt][ne][2 * rr] * inv;
                v.y = O[mt][ne][2 * rr + 1] * inv;
                *(float2*)(op + 8 * ne) = v;
            }
        }
    }
}

extern "C" void kernel_launch(void* const* d_in, const int* in_sizes, int n_in,
                              void* d_out, int out_size)
{
    const float* qkv = (const float*)d_in[0];
    float* out = (float*)d_out;

    cudaFuncSetAttribute(flex_attn_mma,
                         cudaFuncAttributeMaxDynamicSharedMemorySize, SMEM_BYTES);

    dim3 grid(Lc / BM, 2 * Hc);  // 16 q-tiles x 32 (b,h)
    flex_attn_mma<<<grid, THREADS, SMEM_BYTES>>>(qkv, out);
}

// round 14
// speedup vs baseline: 1.4731x; 1.0277x over previous
#include <cuda_runtime.h>
#include <cuda_bf16.h>
#include <stdint.h>

// FlexAttention sliding-window + ALiBi via mma.sync bf16 hi/lo split.
// B=2, L=2048, H=16, E=64, W=1024. qkv [B,L,3,H,E] f32 -> out [B,L,H,E] f32.
//
// R14: 8 warps = 4 m-groups x 2 n-groups. Each warp: 32x32 S block
// (4 n-tiles, one ks loop -> A-frags loaded once), fused epilogue + PV over
// its 2 16-k chunks (PV partial over 32 k). Cross-warp O/ls add via smem
// (reuses K/V region after the main loop). 64KB smem, launch_bounds(256,2)
// -> 16 warps/SM. m16n8k16 bf16 MMA, hi/lo split (3 MMAs/product),
// fixed-shift softmax p = 2^(s*log2e - 16), XOR-swizzled smem.

#define LOG2E 1.44269504088896f

constexpr int Lc = 2048, Hc = 16, Ec = 64, Wc = 1024;
constexpr int BM = 128, BN = 64, THREADS = 256;
constexpr int TOK = 3072;  // floats per token

// word offsets (uint32 units). bf16 tiles: pitch 32 words (64 bf16), XOR swizzle.
constexpr int OQH = 0;       // Q hi [128 rows][32w]
constexpr int OQL = 4096;    // Q lo
constexpr int OKH = 8192;    // K hi [64][32w]   (rows = k, words = e-pairs)
constexpr int OKL = 10240;
constexpr int OVH = 12288;   // V^T hi [64 e][32w] (words = k-pairs)
constexpr int OVL = 14336;
constexpr int SMEM_WORDS = 16384;
constexpr int SMEM_BYTES = SMEM_WORDS * 4;  // 65536

__device__ __forceinline__ float ex2f(float x) {
    float y; asm("ex2.approx.ftz.f32 %0,%1;" : "=f"(y) : "f"(x)); return y;
}
// pack (a -> low half, b -> high half) as bf16x2, plus residual pack
__device__ __forceinline__ void splitpk(float a, float b, uint32_t& hi, uint32_t& lo) {
    uint32_t hw;
    asm("cvt.rn.bf16x2.f32 %0,%1,%2;" : "=r"(hw) : "f"(b), "f"(a));
    float ra = a - __uint_as_float(hw << 16);
    float rb = b - __uint_as_float(hw & 0xffff0000u);
    uint32_t lw;
    asm("cvt.rn.bf16x2.f32 %0,%1,%2;" : "=r"(lw) : "f"(rb), "f"(ra));
    hi = hw; lo = lw;
}
__device__ __forceinline__ void mma16816(float c[4], const uint32_t a[4],
                                         uint32_t b0, uint32_t b1) {
    asm volatile(
        "mma.sync.aligned.m16n8k16.row.col.f32.bf16.bf16.f32 "
        "{%0,%1,%2,%3},{%4,%5,%6,%7},{%8,%9},{%0,%1,%2,%3};"
        : "+f"(c[0]), "+f"(c[1]), "+f"(c[2]), "+f"(c[3])
        : "r"(a[0]), "r"(a[1]), "r"(a[2]), "r"(a[3]), "r"(b0), "r"(b1));
}

__global__ __launch_bounds__(THREADS, 2) void flex_attn_mma(
    const float* __restrict__ qkv, float* __restrict__ out)
{
    extern __shared__ uint32_t smw[];
    float* smf = (float*)smw;
    const int tid = threadIdx.x, wid = tid >> 5, lane = tid & 31;
    const int g = lane >> 2, qd = lane & 3;          // mma groupID / tig
    const uint32_t xg = (uint32_t)g << 2;            // row swizzle (row&7 == g)
    const int mw = wid & 3, nw = wid >> 2;           // m-group / n-group
    const int m0 = 32 * mw;                          // warp's 32-row m-tile pair

    const int qtile = (int)gridDim.x - 1 - (int)blockIdx.x;  // heavy tiles first
    const int b = blockIdx.y >> 4, h = blockIdx.y & 15;
    const int q0 = qtile * BM;

    const float slope = ex2f(-0.5f * (float)(h + 1));
    const float sl2 = slope * LOG2E;
    const float qscale = 0.125f * LOG2E;

    const float* base = qkv + (int64_t)b * Lc * TOK + h * 64;
    const float* qb = base;
    const float* kb = base + 1024;
    const float* vb = base + 2048;

    const int kt0 = (q0 > Wc - 1) ? ((q0 - (Wc - 1)) >> 6) : 0;
    const int ktEnd = 2 * qtile + 1;

    // loader roles
    const int lr = tid >> 2, lq = tid & 3;           // K: row, 16-float quarter
    const int vkp = tid & 31, vwv = tid >> 5;        // V: k-pair, 8-e slab

    // ---- Q commit: 2 threads per row; scale, split, swizzled STS.128 ----
    {
        const int r = tid >> 1, hh = tid & 1;
        const uint32_t xr = (uint32_t)(r & 7) << 2;
        const float4* src = (const float4*)(qb + (int64_t)(q0 + r) * TOK) + 8 * hh;
        float f[32];
#pragma unroll
        for (int c = 0; c < 8; c++) {
            float4 v = src[c];
            f[4 * c + 0] = v.x * qscale; f[4 * c + 1] = v.y * qscale;
            f[4 * c + 2] = v.z * qscale; f[4 * c + 3] = v.w * qscale;
        }
#pragma unroll
        for (int m = 0; m < 4; m++) {
            uint32_t h4[4], l4[4];
#pragma unroll
            for (int j = 0; j < 4; j++)
                splitpk(f[8 * m + 2 * j], f[8 * m + 2 * j + 1], h4[j], l4[j]);
            uint32_t w = ((uint32_t)(16 * hh + 4 * m)) ^ xr;
            *(uint4*)(smw + OQH + r * 32 + w) = make_uint4(h4[0], h4[1], h4[2], h4[3]);
            *(uint4*)(smw + OQL + r * 32 + w) = make_uint4(l4[0], l4[1], l4[2], l4[3]);
        }
    }

    float O[2][8][4];
#pragma unroll
    for (int mt = 0; mt < 2; mt++)
#pragma unroll
        for (int n = 0; n < 8; n++)
#pragma unroll
            for (int j = 0; j < 4; j++) O[mt][n][j] = 0.f;
    float ls[2][2] = {{0.f, 0.f}, {0.f, 0.f}};

    for (int kt = kt0; kt <= ktEnd; kt++) {
        const int k0 = kt * BN;
        __syncthreads();  // prior-iter K/V reads complete before overwrite

        // ---- K load+convert: LDG.128 x4 -> split -> swizzled STS.128 ----
        {
            const float* ksrc = kb + (int64_t)(k0 + lr) * TOK + lq * 16;
            float f[16];
#pragma unroll
            for (int i = 0; i < 4; i++) {
                float4 v = ((const float4*)ksrc)[i];
                f[4 * i] = v.x; f[4 * i + 1] = v.y; f[4 * i + 2] = v.z; f[4 * i + 3] = v.w;
            }
            const uint32_t xr = (uint32_t)(lr & 7) << 2;
#pragma unroll
            for (int m = 0; m < 2; m++) {
                uint32_t h4[4], l4[4];
#pragma unroll
                for (int j = 0; j < 4; j++)
                    splitpk(f[8 * m + 2 * j], f[8 * m + 2 * j + 1], h4[j], l4[j]);
                uint32_t w = ((uint32_t)(8 * lq + 4 * m)) ^ xr;
                *(uint4*)(smw + OKH + lr * 32 + w) = make_uint4(h4[0], h4[1], h4[2], h4[3]);
                *(uint4*)(smw + OKL + lr * 32 + w) = make_uint4(l4[0], l4[1], l4[2], l4[3]);
            }
        }
        // ---- V load+convert -> V^T: rows 2kp,2kp+1, e slab [8wv, 8wv+8) ----
        {
            const float* r0 = vb + (int64_t)(k0 + 2 * vkp) * TOK + 8 * vwv;
            const float* r1 = r0 + TOK;
            float a0[8], a1[8];
#pragma unroll
            for (int i = 0; i < 2; i++) {
                float4 v0 = ((const float4*)r0)[i], v1 = ((const float4*)r1)[i];
                a0[4 * i] = v0.x; a0[4 * i + 1] = v0.y; a0[4 * i + 2] = v0.z; a0[4 * i + 3] = v0.w;
                a1[4 * i] = v1.x; a1[4 * i + 1] = v1.y; a1[4 * i + 2] = v1.z; a1[4 * i + 3] = v1.w;
            }
#pragma unroll
            for (int j = 0; j < 8; j++) {
                int e = 8 * vwv + j;
                uint32_t hw, lw;
                splitpk(a0[j], a1[j], hw, lw);  // low = even k
                uint32_t w = (uint32_t)vkp ^ ((uint32_t)(e & 7) << 2);
                smw[OVH + e * 32 + w] = hw;
                smw[OVL + e * 32 + w] = lw;
            }
        }
        __syncthreads();  // tiles ready

        // ---- S = Q K^T for the warp's 4 n-tiles (one ks loop, A loaded once) ----
        float S[2][4][4];
#pragma unroll
        for (int mt = 0; mt < 2; mt++)
#pragma unroll
            for (int ni = 0; ni < 4; ni++)
#pragma unroll
                for (int j = 0; j < 4; j++) S[mt][ni][j] = 0.f;

#pragma unroll
        for (int ks = 0; ks < 4; ks++) {
            const uint32_t wa = ((uint32_t)(ks * 8 + qd)) ^ xg;
            const uint32_t wb = wa ^ 4u;
            uint32_t AH[2][4], AL[2][4];
#pragma unroll
            for (int mt = 0; mt < 2; mt++) {
                uint32_t rb0 = (uint32_t)(OQH + (m0 + 16 * mt + g) * 32);
                AH[mt][0] = smw[rb0 + wa];       AH[mt][1] = smw[rb0 + 256 + wa];
                AH[mt][2] = smw[rb0 + wb];       AH[mt][3] = smw[rb0 + 256 + wb];
                uint32_t rb1 = rb0 + (OQL - OQH);
                AL[mt][0] = smw[rb1 + wa];       AL[mt][1] = smw[rb1 + 256 + wa];
                AL[mt][2] = smw[rb1 + wb];       AL[mt][3] = smw[rb1 + 256 + wb];
            }
#pragma unroll
            for (int ni = 0; ni < 4; ni++) {
                const int n = 4 * nw + ni;
                uint32_t kbw = (uint32_t)(OKH + (8 * n + g) * 32);
                uint32_t bh0 = smw[kbw + wa], bh1 = smw[kbw + wb];
                uint32_t bl0 = smw[kbw + 2048 + wa], bl1 = smw[kbw + 2048 + wb];
#pragma unroll
                for (int mt = 0; mt < 2; mt++) {
                    mma16816(S[mt][ni], AH[mt], bh0, bh1);
                    mma16816(S[mt][ni], AH[mt], bl0, bl1);
                    mma16816(S[mt][ni], AL[mt], bh0, bh1);
                }
            }
        }

        // ---- fused epilogue + PV over the warp's 2 16-k chunks ----
        const int qi0 = q0 + m0 + g;
#pragma unroll
        for (int kvi = 0; kvi < 2; kvi++) {
            const int kv = 2 * nw + kvi;  // global 16-k chunk
            uint32_t PH[2][4], PL[2][4];
#pragma unroll
            for (int mt = 0; mt < 2; mt++) {
                const int qi = qi0 + 16 * mt;
#pragma unroll
                for (int nh = 0; nh < 2; nh++) {
                    const int ni = 2 * kvi + nh;
                    const int n = 4 * nw + ni;
                    const int d0 = qi - (k0 + 8 * n + 2 * qd);
                    const float df0 = (float)d0;
                    float e0 = fmaf(-sl2, df0,        S[mt][ni][0] - 16.0f);
                    float e1 = fmaf(-sl2, df0 - 1.0f, S[mt][ni][1] - 16.0f);
                    float e2 = fmaf(-sl2, df0 + 8.0f, S[mt][ni][2] - 16.0f);
                    float e3 = fmaf(-sl2, df0 + 7.0f, S[mt][ni][3] - 16.0f);
                    float p0 = ((unsigned)d0 < 1024u)       ? ex2f(e0) : 0.f;
                    float p1 = ((unsigned)(d0 - 1) < 1024u) ? ex2f(e1) : 0.f;
                    float p2 = ((unsigned)(d0 + 8) < 1024u) ? ex2f(e2) : 0.f;
                    float p3 = ((unsigned)(d0 + 7) < 1024u) ? ex2f(e3) : 0.f;
                    ls[mt][0] += p0 + p1;
                    ls[mt][1] += p2 + p3;
                    splitpk(p0, p1, PH[mt][2 * nh],     PL[mt][2 * nh]);
                    splitpk(p2, p3, PH[mt][2 * nh + 1], PL[mt][2 * nh + 1]);
                }
            }
            const uint32_t wa = ((uint32_t)(kv * 8 + qd)) ^ xg;
            const uint32_t wb = wa ^ 4u;
#pragma unroll
            for (int ne = 0; ne < 8; ne++) {
                uint32_t vbw = (uint32_t)(OVH + (8 * ne + g) * 32);
                uint32_t bh0 = smw[vbw + wa], bh1 = smw[vbw + wb];
                uint32_t bl0 = smw[vbw + 2048 + wa], bl1 = smw[vbw + 2048 + wb];
#pragma unroll
                for (int mt = 0; mt < 2; mt++) {
                    mma16816(O[mt][ne], PH[mt], bh0, bh1);
                    mma16816(O[mt][ne], PH[mt], bl0, bl1);
                    mma16816(O[mt][ne], PL[mt], bh0, bh1);
                }
            }
        }
    }

    // ---- cross-warp (nw) reduction of O and ls via smem, then store ----
    __syncthreads();  // done with K/V tiles; smem reusable
    // layout: [j][mw][lane], j in 0..67 (64 O + 4 ls), stride 128 -> conflict-free
    if (nw == 1) {
#pragma unroll
        for (int mt = 0; mt < 2; mt++)
#pragma unroll
            for (int ne = 0; ne < 8; ne++)
#pragma unroll
                for (int c = 0; c < 4; c++)
                    smf[(mt * 32 + ne * 4 + c) * 128 + mw * 32 + lane] = O[mt][ne][c];
#pragma unroll
        for (int mt = 0; mt < 2; mt++)
#pragma unroll
            for (int rr = 0; rr < 2; rr++)
                smf[(64 + mt * 2 + rr) * 128 + mw * 32 + lane] = ls[mt][rr];
    }
    __syncthreads();
    if (nw == 0) {
#pragma unroll
        for (int mt = 0; mt < 2; mt++)
#pragma unroll
            for (int ne = 0; ne < 8; ne++)
#pragma unroll
                for (int c = 0; c < 4; c++)
                    O[mt][ne][c] += smf[(mt * 32 + ne * 4 + c) * 128 + mw * 32 + lane];
#pragma unroll
        for (int mt = 0; mt < 2; mt++)
#pragma unroll
            for (int rr = 0; rr < 2; rr++)
                ls[mt][rr] += smf[(64 + mt * 2 + rr) * 128 + mw * 32 + lane];

#pragma unroll
        for (int mt = 0; mt < 2; mt++) {
#pragma unroll
            for (int rr = 0; rr < 2; rr++) {
                float s = ls[mt][rr];
                s += __shfl_xor_sync(0xffffffffu, s, 1);
                s += __shfl_xor_sync(0xffffffffu, s, 2);
                const float inv = 1.0f / s;
                const int qrow = q0 + m0 + 16 * mt + g + 8 * rr;
                float* op = out + (((int64_t)b * Lc + qrow) * Hc + h) * Ec + 2 * qd;
#pragma unroll
                for (int ne = 0; ne < 8; ne++) {
                    float2 v;
                    v.x = O[mt][ne][2 * rr] * inv;
                    v.y = O[mt][ne][2 * rr + 1] * inv;
                    *(float2*)(op + 8 * ne) = v;
                }
            }
        }
    }
}

extern "C" void kernel_launch(void* const* d_in, const int* in_sizes, int n_in,
                              void* d_out, int out_size)
{
    const float* qkv = (const float*)d_in[0];
    float* out = (float*)d_out;

    cudaFuncSetAttribute(flex_attn_mma,
                         cudaFuncAttributeMaxDynamicSharedMemorySize, SMEM_BYTES);

    dim3 grid(Lc / BM, 2 * Hc);  // 16 q-tiles x 32 (b,h)
    flex_attn_mma<<<grid, THREADS, SMEM_BYTES>>>(qkv, out);
}

// round 16
// speedup vs baseline: 2.0558x; 1.3956x over previous
#include <cuda_runtime.h>
#include <cuda_fp16.h>
#include <stdint.h>

// FlexAttention sliding-window + ALiBi via mma.sync fp16 (asymmetric split).
// B=2, L=2048, H=16, E=64, W=1024. qkv [B,L,3,H,E] f32 -> out [B,L,H,E] f32.
//
// R16 = R15 with the softmax shift fixed: shift 0 instead of -16.
// With -16, rows whose max score ~ -2 gave p_max ~ 2^-18 -> fp16 SUBNORMAL
// (6 mantissa bits) -> 1-2% row error -> rel_err 2.8e-3. With shift 0,
// p in [2^-3, 2^8] per row-max; all significant weights stay fp16-normal.
//  - S = fp16(Q) * fp16(K): 1 MMA per k-step.
//  - PV = fp16(P) * (Vhi + Vlo): 2 MMAs; lsum accumulated from the ROUNDED
//    P values so normalization matches applied weights exactly.
//  - 128 threads, 4 warps x 32-row m-tiles; direct LDG -> cvt -> STS;
//    40KB smem, launch_bounds(128,3) -> 3 CTAs/SM. XOR-swizzled smem.

#define LOG2E 1.44269504088896f

constexpr int Lc = 2048, Hc = 16, Ec = 64, Wc = 1024;
constexpr int BM = 128, BN = 64, THREADS = 128;
constexpr int TOK = 3072;  // floats per token

// word offsets (uint32 units). fp16 tiles: pitch 32 words (64 fp16), XOR swizzle.
constexpr int OQH = 0;       // Q hi [128 rows][32w]
constexpr int OKH = 4096;    // K hi [64][32w]   (rows = k, words = e-pairs)
constexpr int OVH = 6144;    // V^T hi [64 e][32w] (words = k-pairs)
constexpr int OVL = 8192;    // V^T lo
constexpr int SMEM_WORDS = 10240;
constexpr int SMEM_BYTES = SMEM_WORDS * 4;  // 40960 -> 3+ CTAs/SM

__device__ __forceinline__ float ex2f(float x) {
    float y; asm("ex2.approx.ftz.f32 %0,%1;" : "=f"(y) : "f"(x)); return y;
}
// pack (a -> low half, b -> high half) as fp16x2
__device__ __forceinline__ uint32_t pkh2(float a, float b) {
    uint32_t w; asm("cvt.rn.f16x2.f32 %0,%1,%2;" : "=r"(w) : "f"(b), "f"(a));
    return w;
}
// fp16 hi/lo split of a pair
__device__ __forceinline__ void splith(float a, float b, uint32_t& hi, uint32_t& lo) {
    uint32_t hw = pkh2(a, b);
    float2 bk = __half22float2(*reinterpret_cast<__half2*>(&hw));
    lo = pkh2(a - bk.x, b - bk.y);
    hi = hw;
}
__device__ __forceinline__ void mma16816(float c[4], const uint32_t a[4],
                                         uint32_t b0, uint32_t b1) {
    asm volatile(
        "mma.sync.aligned.m16n8k16.row.col.f32.f16.f16.f32 "
        "{%0,%1,%2,%3},{%4,%5,%6,%7},{%8,%9},{%0,%1,%2,%3};"
        : "+f"(c[0]), "+f"(c[1]), "+f"(c[2]), "+f"(c[3])
        : "r"(a[0]), "r"(a[1]), "r"(a[2]), "r"(a[3]), "r"(b0), "r"(b1));
}

__global__ __launch_bounds__(THREADS, 3) void flex_attn_mma(
    const float* __restrict__ qkv, float* __restrict__ out)
{
    extern __shared__ uint32_t smw[];
    const int tid = threadIdx.x, wid = tid >> 5, lane = tid & 31;
    const int g = lane >> 2, qd = lane & 3;          // mma groupID / tig
    const uint32_t xg = (uint32_t)g << 2;            // row swizzle (row&7 == g)
    const int m0 = 32 * wid;                         // warp's 32-row m-tile pair

    const int qtile = (int)gridDim.x - 1 - (int)blockIdx.x;  // heavy tiles first
    const int b = blockIdx.y >> 4, h = blockIdx.y & 15;
    const int q0 = qtile * BM;

    const float slope = ex2f(-0.5f * (float)(h + 1));
    const float sl2 = slope * LOG2E;
    const float qscale = 0.125f * LOG2E;

    const float* base = qkv + (int64_t)b * Lc * TOK + h * 64;
    const float* qb = base;
    const float* kb = base + 1024;
    const float* vb = base + 2048;

    const int kt0 = (q0 > Wc - 1) ? ((q0 - (Wc - 1)) >> 6) : 0;
    const int ktEnd = 2 * qtile + 1;

    // loader roles
    const int kr = tid >> 1, khh = tid & 1;           // K: row, 32-float half
    const int vkp = tid & 31, vwv = tid >> 5;         // V: k-pair, 16-e slab

    // ---- Q commit: thread = row; scale, fp16 pack, swizzled STS.128 ----
    {
        const int r = tid;
        const uint32_t xr = (uint32_t)(r & 7) << 2;
        const float4* src = (const float4*)(qb + (int64_t)(q0 + r) * TOK);
        float f[64];
#pragma unroll
        for (int c = 0; c < 16; c++) {
            float4 v = src[c];
            f[4 * c + 0] = v.x * qscale; f[4 * c + 1] = v.y * qscale;
            f[4 * c + 2] = v.z * qscale; f[4 * c + 3] = v.w * qscale;
        }
#pragma unroll
        for (int m = 0; m < 8; m++) {
            uint32_t h4[4];
#pragma unroll
            for (int j = 0; j < 4; j++)
                h4[j] = pkh2(f[8 * m + 2 * j], f[8 * m + 2 * j + 1]);
            uint32_t w = ((uint32_t)(4 * m)) ^ xr;
            *(uint4*)(smw + OQH + r * 32 + w) = make_uint4(h4[0], h4[1], h4[2], h4[3]);
        }
    }

    float O[2][8][4];
#pragma unroll
    for (int mt = 0; mt < 2; mt++)
#pragma unroll
        for (int n = 0; n < 8; n++)
#pragma unroll
            for (int j = 0; j < 4; j++) O[mt][n][j] = 0.f;
    float ls[2][2] = {{0.f, 0.f}, {0.f, 0.f}};

    for (int kt = kt0; kt <= ktEnd; kt++) {
        const int k0 = kt * BN;
        __syncthreads();  // prior-iter K/V reads complete before overwrite

        // ---- K load+convert: LDG.128 x8 -> fp16 -> swizzled STS.128 ----
        {
            const float* ksrc = kb + (int64_t)(k0 + kr) * TOK + khh * 32;
            float f[32];
#pragma unroll
            for (int i = 0; i < 8; i++) {
                float4 v = ((const float4*)ksrc)[i];
                f[4 * i] = v.x; f[4 * i + 1] = v.y; f[4 * i + 2] = v.z; f[4 * i + 3] = v.w;
            }
            const uint32_t xr = (uint32_t)(kr & 7) << 2;
#pragma unroll
            for (int m = 0; m < 4; m++) {
                uint32_t h4[4];
#pragma unroll
                for (int j = 0; j < 4; j++)
                    h4[j] = pkh2(f[8 * m + 2 * j], f[8 * m + 2 * j + 1]);
                uint32_t w = ((uint32_t)(16 * khh + 4 * m)) ^ xr;
                *(uint4*)(smw + OKH + kr * 32 + w) = make_uint4(h4[0], h4[1], h4[2], h4[3]);
            }
        }
        // ---- V load+convert -> V^T hi/lo: rows 2kp,2kp+1, e slab 16wv.. ----
        {
            const float* r0 = vb + (int64_t)(k0 + 2 * vkp) * TOK + 16 * vwv;
            const float* r1 = r0 + TOK;
            float a0[16], a1[16];
#pragma unroll
            for (int i = 0; i < 4; i++) {
                float4 v0 = ((const float4*)r0)[i], v1 = ((const float4*)r1)[i];
                a0[4 * i] = v0.x; a0[4 * i + 1] = v0.y; a0[4 * i + 2] = v0.z; a0[4 * i + 3] = v0.w;
                a1[4 * i] = v1.x; a1[4 * i + 1] = v1.y; a1[4 * i + 2] = v1.z; a1[4 * i + 3] = v1.w;
            }
#pragma unroll
            for (int j = 0; j < 16; j++) {
                int e = 16 * vwv + j;
                uint32_t hw, lw;
                splith(a0[j], a1[j], hw, lw);  // low = even k
                uint32_t w = (uint32_t)vkp ^ ((uint32_t)(e & 7) << 2);
                smw[OVH + e * 32 + w] = hw;
                smw[OVL + e * 32 + w] = lw;
            }
        }
        __syncthreads();  // tiles ready

        // ---- S = Q K^T : 4 k-steps x 8 n-tiles x 1 MMA ----
        float S[2][8][4];
#pragma unroll
        for (int mt = 0; mt < 2; mt++)
#pragma unroll
            for (int n = 0; n < 8; n++)
#pragma unroll
                for (int j = 0; j < 4; j++) S[mt][n][j] = 0.f;

#pragma unroll
        for (int ks = 0; ks < 4; ks++) {
            const uint32_t wa = ((uint32_t)(ks * 8 + qd)) ^ xg;
            const uint32_t wb = wa ^ 4u;
            uint32_t AH[2][4];
#pragma unroll
            for (int mt = 0; mt < 2; mt++) {
                uint32_t rb0 = (uint32_t)(OQH + (m0 + 16 * mt + g) * 32);
                AH[mt][0] = smw[rb0 + wa];       AH[mt][1] = smw[rb0 + 256 + wa];
                AH[mt][2] = smw[rb0 + wb];       AH[mt][3] = smw[rb0 + 256 + wb];
            }
#pragma unroll
            for (int n = 0; n < 8; n++) {
                uint32_t kbw = (uint32_t)(OKH + (8 * n + g) * 32);
                uint32_t bh0 = smw[kbw + wa], bh1 = smw[kbw + wb];
#pragma unroll
                for (int mt = 0; mt < 2; mt++)
                    mma16816(S[mt][n], AH[mt], bh0, bh1);
            }
        }

        // ---- fused epilogue + PV per 16-k chunk ----
        const int qi0 = q0 + m0 + g;
#pragma unroll
        for (int kv = 0; kv < 4; kv++) {
            uint32_t PH[2][4];
#pragma unroll
            for (int mt = 0; mt < 2; mt++) {
                const int qi = qi0 + 16 * mt;
#pragma unroll
                for (int nh = 0; nh < 2; nh++) {
                    const int n = 2 * kv + nh;
                    const int d0 = qi - (k0 + 8 * n + 2 * qd);
                    const float df0 = (float)d0;
                    float e0 = fmaf(-sl2, df0,        S[mt][n][0]);
                    float e1 = fmaf(-sl2, df0 - 1.0f, S[mt][n][1]);
                    float e2 = fmaf(-sl2, df0 + 8.0f, S[mt][n][2]);
                    float e3 = fmaf(-sl2, df0 + 7.0f, S[mt][n][3]);
                    float p0 = ((unsigned)d0 < 1024u)       ? ex2f(e0) : 0.f;
                    float p1 = ((unsigned)(d0 - 1) < 1024u) ? ex2f(e1) : 0.f;
                    float p2 = ((unsigned)(d0 + 8) < 1024u) ? ex2f(e2) : 0.f;
                    float p3 = ((unsigned)(d0 + 7) < 1024u) ? ex2f(e3) : 0.f;
                    uint32_t w01 = pkh2(p0, p1);
                    uint32_t w23 = pkh2(p2, p3);
                    PH[mt][2 * nh]     = w01;
                    PH[mt][2 * nh + 1] = w23;
                    // lsum from ROUNDED weights so normalization matches PV
                    float2 b01 = __half22float2(*reinterpret_cast<__half2*>(&w01));
                    float2 b23 = __half22float2(*reinterpret_cast<__half2*>(&w23));
                    ls[mt][0] += b01.x + b01.y;
                    ls[mt][1] += b23.x + b23.y;
                }
            }
            const uint32_t wa = ((uint32_t)(kv * 8 + qd)) ^ xg;
            const uint32_t wb = wa ^ 4u;
#pragma unroll
            for (int ne = 0; ne < 8; ne++) {
                uint32_t vbw = (uint32_t)(OVH + (8 * ne + g) * 32);
                uint32_t bh0 = smw[vbw + wa], bh1 = smw[vbw + wb];
                uint32_t bl0 = smw[vbw + 2048 + wa], bl1 = smw[vbw + 2048 + wb];
#pragma unroll
                for (int mt = 0; mt < 2; mt++) {
                    mma16816(O[mt][ne], PH[mt], bh0, bh1);
                    mma16816(O[mt][ne], PH[mt], bl0, bl1);
                }
            }
        }
    }

    // ---- normalize + store ----
#pragma unroll
    for (int mt = 0; mt < 2; mt++) {
#pragma unroll
        for (int rr = 0; rr < 2; rr++) {
            float s = ls[mt][rr];
            s += __shfl_xor_sync(0xffffffffu, s, 1);
            s += __shfl_xor_sync(0xffffffffu, s, 2);
            const float inv = 1.0f / s;
            const int qrow = q0 + m0 + 16 * mt + g + 8 * rr;
            float* op = out + (((int64_t)b * Lc + qrow) * Hc + h) * Ec + 2 * qd;
#pragma unroll
            for (int ne = 0; ne < 8; ne++) {
                float2 v;
                v.x = O[mt][ne][2 * rr] * inv;
                v.y = O[mt][ne][2 * rr + 1] * inv;
                *(float2*)(op + 8 * ne) = v;
            }
        }
    }
}

extern "C" void kernel_launch(void* const* d_in, const int* in_sizes, int n_in,
                              void* d_out, int out_size)
{
    const float* qkv = (const float*)d_in[0];
    float* out = (float*)d_out;

    cudaFuncSetAttribute(flex_attn_mma,
                         cudaFuncAttributeMaxDynamicSharedMemorySize, SMEM_BYTES);

    dim3 grid(Lc / BM, 2 * Hc);  // 16 q-tiles x 32 (b,h)
    flex_attn_mma<<<grid, THREADS, SMEM_BYTES>>>(qkv, out);
}

// round 17
// speedup vs baseline: 2.2103x; 1.0752x over previous
#include <cuda_runtime.h>
#include <cuda_fp16.h>
#include <stdint.h>

// FlexAttention sliding-window + ALiBi via mma.sync fp16.
// B=2, L=2048, H=16, E=64, W=1024. qkv [B,L,3,H,E] f32 -> out [B,L,H,E] f32.
//
// R17 = R16 + (a) cp.async f32 staging double-phase (next tile's K/V load
// overlapped with MMA/epilogue; wait at loop top) and (b) V-lo split dropped
// (PV = fp16(P)*fp16(V), 1 MMA; V rounding ~1.4e-4 rms, budget holds).
//  - S = fp16(Q)*fp16(K): 1 MMA/k-step. MMAs/warp/iter: 128.
//  - lsum accumulated from ROUNDED P so normalization matches applied weights.
//  - shift-0 softmax p = 2^(s - slope*d) (fp16-normal range; R15's -16 shift
//    hit fp16 subnormals).
//  - 128 threads, 4 warps x 32-row m-tiles, 67.6KB smem -> 3 CTAs/SM.

#define LOG2E 1.44269504088896f

constexpr int Lc = 2048, Hc = 16, Ec = 64, Wc = 1024;
constexpr int BM = 128, BN = 64, THREADS = 128;
constexpr int TOK = 3072;  // floats per token

// word offsets (uint32 units). fp16 tiles: pitch 32 words (64 fp16), XOR swizzle.
constexpr int OQH = 0;        // Q [128 rows][32w]
constexpr int OKH = 4096;     // K [64][32w]   (rows = k, words = e-pairs)
constexpr int OVH = 6144;     // V^T [64 e][32w] (words = k-pairs)
constexpr int KSTG = 8192;    // K f32 staging [64][68]
constexpr int VSTG = KSTG + 64 * 68;
constexpr int SMEM_WORDS = VSTG + 64 * 68;
constexpr int SMEM_BYTES = SMEM_WORDS * 4;  // 67584 -> 3 CTAs/SM

__device__ __forceinline__ uint32_t s2u(const void* p) {
    uint32_t a;
    asm("{.reg .u64 t; cvta.to.shared.u64 t,%1; cvt.u32.u64 %0,t;}" : "=r"(a) : "l"(p));
    return a;
}
__device__ __forceinline__ float ex2f(float x) {
    float y; asm("ex2.approx.ftz.f32 %0,%1;" : "=f"(y) : "f"(x)); return y;
}
// pack (a -> low half, b -> high half) as fp16x2
__device__ __forceinline__ uint32_t pkh2(float a, float b) {
    uint32_t w; asm("cvt.rn.f16x2.f32 %0,%1,%2;" : "=r"(w) : "f"(b), "f"(a));
    return w;
}
__device__ __forceinline__ void mma16816(float c[4], const uint32_t a[4],
                                         uint32_t b0, uint32_t b1) {
    asm volatile(
        "mma.sync.aligned.m16n8k16.row.col.f32.f16.f16.f32 "
        "{%0,%1,%2,%3},{%4,%5,%6,%7},{%8,%9},{%0,%1,%2,%3};"
        : "+f"(c[0]), "+f"(c[1]), "+f"(c[2]), "+f"(c[3])
        : "r"(a[0]), "r"(a[1]), "r"(a[2]), "r"(a[3]), "r"(b0), "r"(b1));
}
__device__ __forceinline__ void cp16(uint32_t dst, const void* src) {
    asm volatile("cp.async.cg.shared.global [%0], [%1], 16;" :: "r"(dst), "l"(src));
}
#define CP_COMMIT() asm volatile("cp.async.commit_group;" ::: "memory")
#define CP_WAIT0()  asm volatile("cp.async.wait_group 0;" ::: "memory")

__global__ __launch_bounds__(THREADS, 3) void flex_attn_mma(
    const float* __restrict__ qkv, float* __restrict__ out)
{
    extern __shared__ uint32_t smw[];
    const uint32_t sb = s2u(smw);
    const int tid = threadIdx.x, wid = tid >> 5, lane = tid & 31;
    const int g = lane >> 2, qd = lane & 3;          // mma groupID / tig
    const uint32_t xg = (uint32_t)g << 2;            // row swizzle (row&7 == g)
    const int m0 = 32 * wid;                         // warp's 32-row m-tile pair

    const int qtile = (int)gridDim.x - 1 - (int)blockIdx.x;  // heavy tiles first
    const int b = blockIdx.y >> 4, h = blockIdx.y & 15;
    const int q0 = qtile * BM;

    const float slope = ex2f(-0.5f * (float)(h + 1));
    const float sl2 = slope * LOG2E;
    const float qscale = 0.125f * LOG2E;

    const float* base = qkv + (int64_t)b * Lc * TOK + h * 64;
    const float* qb = base;
    const float* kb = base + 1024;
    const float* vb = base + 2048;

    const int kt0 = (q0 > Wc - 1) ? ((q0 - (Wc - 1)) >> 6) : 0;
    const int ktEnd = 2 * qtile + 1;

    // loader roles: 2 threads per row, 32-float halves (for staging cp.async
    // and K convert); V convert uses (k-pair, e-slab).
    const int kr = tid >> 1, khh = tid & 1;
    const int vkp = tid & 31, vwv = tid >> 5;  // k-pair 0..31, e-slab 0..3 (16 e)

    // ---- prologue: issue cp.async for first K/V tile ----
    {
        const int k0 = kt0 * BN;
        const float* ksrc = kb + (int64_t)(k0 + kr) * TOK + khh * 32;
        const float* vsrc = vb + (int64_t)(k0 + kr) * TOK + khh * 32;
        uint32_t kdst = sb + (uint32_t)(KSTG + kr * 68 + khh * 32) * 4u;
        uint32_t vdst = sb + (uint32_t)(VSTG + kr * 68 + khh * 32) * 4u;
#pragma unroll
        for (int i = 0; i < 8; i++) cp16(kdst + 16 * i, ksrc + 4 * i);
#pragma unroll
        for (int i = 0; i < 8; i++) cp16(vdst + 16 * i, vsrc + 4 * i);
        CP_COMMIT();
    }

    // ---- Q commit: thread = row; scale, fp16 pack, swizzled STS.128 ----
    {
        const int r = tid;
        const uint32_t xr = (uint32_t)(r & 7) << 2;
        const float4* src = (const float4*)(qb + (int64_t)(q0 + r) * TOK);
        float f[64];
#pragma unroll
        for (int c = 0; c < 16; c++) {
            float4 v = src[c];
            f[4 * c + 0] = v.x * qscale; f[4 * c + 1] = v.y * qscale;
            f[4 * c + 2] = v.z * qscale; f[4 * c + 3] = v.w * qscale;
        }
#pragma unroll
        for (int m = 0; m < 8; m++) {
            uint32_t h4[4];
#pragma unroll
            for (int j = 0; j < 4; j++)
                h4[j] = pkh2(f[8 * m + 2 * j], f[8 * m + 2 * j + 1]);
            uint32_t w = ((uint32_t)(4 * m)) ^ xr;
            *(uint4*)(smw + OQH + r * 32 + w) = make_uint4(h4[0], h4[1], h4[2], h4[3]);
        }
    }

    float O[2][8][4];
#pragma unroll
    for (int mt = 0; mt < 2; mt++)
#pragma unroll
        for (int n = 0; n < 8; n++)
#pragma unroll
            for (int j = 0; j < 4; j++) O[mt][n][j] = 0.f;
    float ls[2][2] = {{0.f, 0.f}, {0.f, 0.f}};

    for (int kt = kt0; kt <= ktEnd; kt++) {
        const int k0 = kt * BN;

        CP_WAIT0();
        __syncthreads();  // staging arrived; prior-iter tile reads complete

        // ---- convert K: staging f32 -> fp16 -> swizzled STS.128 ----
        {
            const float4* srow = (const float4*)((const float*)(smw + KSTG) + kr * 68 + khh * 32);
            float f[32];
#pragma unroll
            for (int i = 0; i < 8; i++) {
                float4 v = srow[i];
                f[4 * i] = v.x; f[4 * i + 1] = v.y; f[4 * i + 2] = v.z; f[4 * i + 3] = v.w;
            }
            const uint32_t xr = (uint32_t)(kr & 7) << 2;
#pragma unroll
            for (int m = 0; m < 4; m++) {
                uint32_t h4[4];
#pragma unroll
                for (int j = 0; j < 4; j++)
                    h4[j] = pkh2(f[8 * m + 2 * j], f[8 * m + 2 * j + 1]);
                uint32_t w = ((uint32_t)(16 * khh + 4 * m)) ^ xr;
                *(uint4*)(smw + OKH + kr * 32 + w) = make_uint4(h4[0], h4[1], h4[2], h4[3]);
            }
        }
        // ---- convert V -> V^T: rows 2kp,2kp+1, e slab [16wv,16wv+16) ----
        {
            const float* r0 = (const float*)(smw + VSTG) + (2 * vkp) * 68 + 16 * vwv;
            const float* r1 = r0 + 68;
            float a0[16], a1[16];
#pragma unroll
            for (int i = 0; i < 4; i++) {
                float4 v0 = ((const float4*)r0)[i], v1 = ((const float4*)r1)[i];
                a0[4 * i] = v0.x; a0[4 * i + 1] = v0.y; a0[4 * i + 2] = v0.z; a0[4 * i + 3] = v0.w;
                a1[4 * i] = v1.x; a1[4 * i + 1] = v1.y; a1[4 * i + 2] = v1.z; a1[4 * i + 3] = v1.w;
            }
#pragma unroll
            for (int j = 0; j < 16; j++) {
                int e = 16 * vwv + j;
                uint32_t w = (uint32_t)vkp ^ ((uint32_t)(e & 7) << 2);
                smw[OVH + e * 32 + w] = pkh2(a0[j], a1[j]);  // low = even k
            }
        }
        __syncthreads();  // tiles ready; staging free

        // ---- issue cp.async for next tile (hides under MMA/epilogue) ----
        if (kt < ktEnd) {
            const int kn = k0 + BN;
            const float* ksrc = kb + (int64_t)(kn + kr) * TOK + khh * 32;
            const float* vsrc = vb + (int64_t)(kn + kr) * TOK + khh * 32;
            uint32_t kdst = sb + (uint32_t)(KSTG + kr * 68 + khh * 32) * 4u;
            uint32_t vdst = sb + (uint32_t)(VSTG + kr * 68 + khh * 32) * 4u;
#pragma unroll
            for (int i = 0; i < 8; i++) cp16(kdst + 16 * i, ksrc + 4 * i);
#pragma unroll
            for (int i = 0; i < 8; i++) cp16(vdst + 16 * i, vsrc + 4 * i);
            CP_COMMIT();
        }

        // ---- S = Q K^T : 4 k-steps x 8 n-tiles x 1 MMA ----
        float S[2][8][4];
#pragma unroll
        for (int mt = 0; mt < 2; mt++)
#pragma unroll
            for (int n = 0; n < 8; n++)
#pragma unroll
                for (int j = 0; j < 4; j++) S[mt][n][j] = 0.f;

#pragma unroll
        for (int ks = 0; ks < 4; ks++) {
            const uint32_t wa = ((uint32_t)(ks * 8 + qd)) ^ xg;
            const uint32_t wb = wa ^ 4u;
            uint32_t AH[2][4];
#pragma unroll
            for (int mt = 0; mt < 2; mt++) {
                uint32_t rb0 = (uint32_t)(OQH + (m0 + 16 * mt + g) * 32);
                AH[mt][0] = smw[rb0 + wa];       AH[mt][1] = smw[rb0 + 256 + wa];
                AH[mt][2] = smw[rb0 + wb];       AH[mt][3] = smw[rb0 + 256 + wb];
            }
#pragma unroll
            for (int n = 0; n < 8; n++) {
                uint32_t kbw = (uint32_t)(OKH + (8 * n + g) * 32);
                uint32_t bh0 = smw[kbw + wa], bh1 = smw[kbw + wb];
#pragma unroll
                for (int mt = 0; mt < 2; mt++)
                    mma16816(S[mt][n], AH[mt], bh0, bh1);
            }
        }

        // ---- fused epilogue + PV per 16-k chunk ----
        const int qi0 = q0 + m0 + g;
#pragma unroll
        for (int kv = 0; kv < 4; kv++) {
            uint32_t PH[2][4];
#pragma unroll
            for (int mt = 0; mt < 2; mt++) {
                const int qi = qi0 + 16 * mt;
#pragma unroll
                for (int nh = 0; nh < 2; nh++) {
                    const int n = 2 * kv + nh;
                    const int d0 = qi - (k0 + 8 * n + 2 * qd);
                    const float df0 = (float)d0;
                    float e0 = fmaf(-sl2, df0,        S[mt][n][0]);
                    float e1 = fmaf(-sl2, df0 - 1.0f, S[mt][n][1]);
                    float e2 = fmaf(-sl2, df0 + 8.0f, S[mt][n][2]);
                    float e3 = fmaf(-sl2, df0 + 7.0f, S[mt][n][3]);
                    float p0 = ((unsigned)d0 < 1024u)       ? ex2f(e0) : 0.f;
                    float p1 = ((unsigned)(d0 - 1) < 1024u) ? ex2f(e1) : 0.f;
                    float p2 = ((unsigned)(d0 + 8) < 1024u) ? ex2f(e2) : 0.f;
                    float p3 = ((unsigned)(d0 + 7) < 1024u) ? ex2f(e3) : 0.f;
                    uint32_t w01 = pkh2(p0, p1);
                    uint32_t w23 = pkh2(p2, p3);
                    PH[mt][2 * nh]     = w01;
                    PH[mt][2 * nh + 1] = w23;
                    // lsum from ROUNDED weights so normalization matches PV
                    float2 b01 = __half22float2(*reinterpret_cast<__half2*>(&w01));
                    float2 b23 = __half22float2(*reinterpret_cast<__half2*>(&w23));
                    ls[mt][0] += b01.x + b01.y;
                    ls[mt][1] += b23.x + b23.y;
                }
            }
            const uint32_t wa = ((uint32_t)(kv * 8 + qd)) ^ xg;
            const uint32_t wb = wa ^ 4u;
#pragma unroll
            for (int ne = 0; ne < 8; ne++) {
                uint32_t vbw = (uint32_t)(OVH + (8 * ne + g) * 32);
                uint32_t bh0 = smw[vbw + wa], bh1 = smw[vbw + wb];
#pragma unroll
                for (int mt = 0; mt < 2; mt++)
                    mma16816(O[mt][ne], PH[mt], bh0, bh1);
            }
        }
    }

    // ---- normalize + store ----
#pragma unroll
    for (int mt = 0; mt < 2; mt++) {
#pragma unroll
        for (int rr = 0; rr < 2; rr++) {
            float s = ls[mt][rr];
            s += __shfl_xor_sync(0xffffffffu, s, 1);
            s += __shfl_xor_sync(0xffffffffu, s, 2);
            const float inv = 1.0f / s;
            const int qrow = q0 + m0 + 16 * mt + g + 8 * rr;
            float* op = out + (((int64_t)b * Lc + qrow) * Hc + h) * Ec + 2 * qd;
#pragma unroll
            for (int ne = 0; ne < 8; ne++) {
                float2 v;
                v.x = O[mt][ne][2 * rr] * inv;
                v.y = O[mt][ne][2 * rr + 1] * inv;
                *(float2*)(op + 8 * ne) = v;
            }
        }
    }
}

extern "C" void kernel_launch(void* const* d_in, const int* in_sizes, int n_in,
                              void* d_out, int out_size)
{
    const float* qkv = (const float*)d_in[0];
    float* out = (float*)d_out;

    cudaFuncSetAttribute(flex_attn_mma,
                         cudaFuncAttributeMaxDynamicSharedMemorySize, SMEM_BYTES);

    dim3 grid(Lc / BM, 2 * Hc);  // 16 q-tiles x 32 (b,h)
    flex_attn_mma<<<grid, THREADS, SMEM_BYTES>>>(qkv, out);
}